// round 4
// baseline (speedup 1.0000x reference)
#include <cuda_runtime.h>
#include <cuda_bf16.h>
#include <cstdint>

// ---------------------------------------------------------------------------
// LlamaMLP with MX quantization (fp6_e2m3 activations, fp4_e2m1 weights).
// x[4096,2048], w_gate[8192,2048], w_up[8192,2048], w_down[2048,8192]
// out[4096,2048] fp32.
//
// MX-quantized values (<=4 significand bits * power-of-2 block scale) are
// EXACTLY representable in bf16 => quantize once to bf16, run bf16 tensor-core
// GEMMs with fp32 accumulation (products exact, only sum order differs).
//
// Pipeline:
//   1) quant x -> Aq (fp6 grid), quant weights -> Wgq/Wuq/Wdq (fp4 grid)
//   2) fused kernel: gate=Aq@Wgq^T, up=Aq@Wuq^T, epilogue silu(gate)*up
//      + MX fp6 quant along I, store bf16 -> Iq (no fp32 round-trip)
//   3) out = Iq @ Wdq^T
// ---------------------------------------------------------------------------

#define S_DIM 4096
#define H_DIM 2048
#define I_DIM 8192

// Scratch: 176 MB of static __device__ globals (no runtime allocation).
__device__ __align__(256) __nv_bfloat16 g_Aq [(size_t)S_DIM * H_DIM];  // 16 MB
__device__ __align__(256) __nv_bfloat16 g_Wgq[(size_t)I_DIM * H_DIM];  // 32 MB
__device__ __align__(256) __nv_bfloat16 g_Wuq[(size_t)I_DIM * H_DIM];  // 32 MB
__device__ __align__(256) __nv_bfloat16 g_Wdq[(size_t)H_DIM * I_DIM];  // 32 MB
__device__ __align__(256) __nv_bfloat16 g_Iq [(size_t)S_DIM * I_DIM];  // 64 MB

// ---------------------------------------------------------------------------
// Quantization helpers (exact emulation of the reference semantics).
//   e2 formats: min_exp = -(2^(ebits-1))+2 = 0  -> priv = max(floor(log2|x|),0)
//   qs = 2^(priv-mfrac); q = rint(x/qs)*qs; clip(+-max_norm)
//   ilogbf == exact floor(log2); rintf == round-half-to-even == jnp.round.
// ---------------------------------------------------------------------------
__device__ __forceinline__ float quant_elem(float x, int mfrac, float maxn) {
    float ax = fabsf(x);
    int priv = (ax == 0.0f) ? 0 : ilogbf(ax);
    priv = max(priv, 0);
    float qs = ldexpf(1.0f, priv - mfrac);
    float q = rintf(x / qs) * qs;
    return fminf(fmaxf(q, -maxn), maxn);
}

__device__ __forceinline__ int block_se(float amax) {
    int se = (amax == 0.0f) ? 0 : ilogbf(amax);  // floor(log2(max)); 0 -> log2(1)=0
    se -= 2;                                     // emax_elem = 2
    return min(max(se, -127), 127);              // SCALE_EMAX clamp
}

__device__ __forceinline__ float block_quant(float v, int se, int mfrac, float maxn) {
    float inv = ldexpf(1.0f, -se);
    float sc  = ldexpf(1.0f,  se);
    return quant_elem(v * inv, mfrac, maxn) * sc;
}

// Warp-cooperative MX quant: 32 lanes == one MX block along the last axis.
__global__ void quant_mx_kernel(const float* __restrict__ in, int dst,
                                long nblocks, int mfrac, float maxn) {
    __nv_bfloat16* out = (dst == 0) ? g_Aq : (dst == 1) ? g_Wgq
                       : (dst == 2) ? g_Wuq : g_Wdq;
    int lane = threadIdx.x & 31;
    long w = (long)blockIdx.x * (blockDim.x >> 5) + (threadIdx.x >> 5);
    long total = (long)gridDim.x * (blockDim.x >> 5);
    for (; w < nblocks; w += total) {
        long idx = w * 32 + lane;
        float v = in[idx];
        float a = fabsf(v);
        #pragma unroll
        for (int o = 16; o; o >>= 1)
            a = fmaxf(a, __shfl_xor_sync(0xffffffffu, a, o));
        int se = block_se(a);
        out[idx] = __float2bfloat16(block_quant(v, se, mfrac, maxn));
    }
}

// ---------------------------------------------------------------------------
// Shared GEMM building blocks: mma.m16n8k16 bf16, cp.async, ldmatrix.
// SMEM rows padded to 40 halves (80 B) -> 20-bank rotation, conflict-free.
// ---------------------------------------------------------------------------
#define LDT 40

__device__ __forceinline__ void cp16(void* d, const void* s) {
    uint32_t da = (uint32_t)__cvta_generic_to_shared(d);
    asm volatile("cp.async.cg.shared.global [%0], [%1], 16;" :: "r"(da), "l"(s));
}
__device__ __forceinline__ void cp_commit() { asm volatile("cp.async.commit_group;"); }
__device__ __forceinline__ void cp_wait1()  { asm volatile("cp.async.wait_group 1;"); }

__device__ __forceinline__ void ldsm4(uint32_t& r0, uint32_t& r1, uint32_t& r2,
                                      uint32_t& r3, const void* p) {
    uint32_t a = (uint32_t)__cvta_generic_to_shared(p);
    asm volatile("ldmatrix.sync.aligned.m8n8.x4.shared.b16 {%0,%1,%2,%3}, [%4];"
                 : "=r"(r0), "=r"(r1), "=r"(r2), "=r"(r3) : "r"(a));
}
__device__ __forceinline__ void mma16816(float* c, const uint32_t* a, const uint32_t* b) {
    asm volatile(
        "mma.sync.aligned.m16n8k16.row.col.f32.bf16.bf16.f32 "
        "{%0,%1,%2,%3}, {%4,%5,%6,%7}, {%8,%9}, {%0,%1,%2,%3};"
        : "+f"(c[0]), "+f"(c[1]), "+f"(c[2]), "+f"(c[3])
        : "r"(a[0]), "r"(a[1]), "r"(a[2]), "r"(a[3]), "r"(b[0]), "r"(b[1]));
}

// ---------------------------------------------------------------------------
// Fused gate/up GEMM + SwiGLU + fp6 MX quant epilogue.
// Tile: 128(M) x 64(N per matrix) x 32(K). 8 warps: 4 over M, 2 over N.
// Each warp's N range (32 cols) == exactly one MX block per row.
// ---------------------------------------------------------------------------
__global__ __launch_bounds__(256) void gemm_gateup_swiglu_kernel(
    const float* __restrict__ dummy /* unused, keeps signature nonempty */) {
    (void)dummy;
    __shared__ __align__(128) __nv_bfloat16 sA [2][128][LDT];
    __shared__ __align__(128) __nv_bfloat16 sBg[2][64][LDT];
    __shared__ __align__(128) __nv_bfloat16 sBu[2][64][LDT];

    const __nv_bfloat16* A  = g_Aq;
    const __nv_bfloat16* Bg = g_Wgq;
    const __nv_bfloat16* Bu = g_Wuq;
    __nv_bfloat16* O = g_Iq;
    const int K = H_DIM;

    int tid = threadIdx.x;
    long bRow = (long)blockIdx.y * 128;
    long bCol = (long)blockIdx.x * 64;
    int warp = tid >> 5, lane = tid & 31;
    int wRow = (warp & 3) * 32;
    int wCol = (warp >> 2) * 32;

    float ag[2][4][4], au[2][4][4];
    #pragma unroll
    for (int i = 0; i < 2; i++)
        #pragma unroll
        for (int j = 0; j < 4; j++)
            #pragma unroll
            for (int k = 0; k < 4; k++) { ag[i][j][k] = 0.0f; au[i][j][k] = 0.0f; }

    const int nK = K / 32;  // 64

    // stage loader
    auto load_stage = [&](int st, int k0) {
        #pragma unroll
        for (int i = 0; i < 2; i++) {
            int idx = i * 256 + tid;
            int r = idx >> 2, c = (idx & 3) * 8;
            cp16(&sA[st][r][c], A + (bRow + r) * (long)K + k0 + c);
        }
        int r = tid >> 2, c = (tid & 3) * 8;
        cp16(&sBg[st][r][c], Bg + (bCol + r) * (long)K + k0 + c);
        cp16(&sBu[st][r][c], Bu + (bCol + r) * (long)K + k0 + c);
    };

    load_stage(0, 0);
    cp_commit();

    for (int kt = 0; kt < nK; ++kt) {
        if (kt + 1 < nK) load_stage((kt + 1) & 1, (kt + 1) * 32);
        cp_commit();   // possibly-empty group keeps wait counts uniform
        cp_wait1();
        __syncthreads();

        int st = kt & 1;
        #pragma unroll
        for (int ks = 0; ks < 32; ks += 16) {
            uint32_t af[2][4];
            #pragma unroll
            for (int mi = 0; mi < 2; mi++) {
                int row = wRow + mi * 16 + (lane & 15);
                int col = ks + ((lane >> 4) << 3);
                ldsm4(af[mi][0], af[mi][1], af[mi][2], af[mi][3], &sA[st][row][col]);
            }
            uint32_t bg[4][2], bu[4][2];
            #pragma unroll
            for (int p = 0; p < 2; p++) {
                int row = wCol + p * 16 + ((lane >> 4) << 3) + (lane & 7);
                int col = ks + ((lane >> 3) & 1) * 8;
                ldsm4(bg[2*p][0], bg[2*p][1], bg[2*p+1][0], bg[2*p+1][1], &sBg[st][row][col]);
                ldsm4(bu[2*p][0], bu[2*p][1], bu[2*p+1][0], bu[2*p+1][1], &sBu[st][row][col]);
            }
            #pragma unroll
            for (int mi = 0; mi < 2; mi++)
                #pragma unroll
                for (int nj = 0; nj < 4; nj++) {
                    mma16816(ag[mi][nj], af[mi], bg[nj]);
                    mma16816(au[mi][nj], af[mi], bu[nj]);
                }
        }
        __syncthreads();
    }

    // ---- Epilogue: silu(gate)*up, MX fp6 quant per 32-wide N block ----
    int g = lane >> 2, tg = lane & 3;
    #pragma unroll
    for (int mi = 0; mi < 2; mi++) {
        // two rows per fragment: rA = base+g (c[0],c[1]), rB = base+g+8 (c[2],c[3])
        float vA[8], vB[8];
        #pragma unroll
        for (int nj = 0; nj < 4; nj++)
            #pragma unroll
            for (int k = 0; k < 2; k++) {
                float gv = ag[mi][nj][k],     uv = au[mi][nj][k];
                vA[nj*2+k] = gv / (1.0f + expf(-gv)) * uv;
                float gv2 = ag[mi][nj][2+k],  uv2 = au[mi][nj][2+k];
                vB[nj*2+k] = gv2 / (1.0f + expf(-gv2)) * uv2;
            }
        float mA = 0.0f, mB = 0.0f;
        #pragma unroll
        for (int i = 0; i < 8; i++) {
            mA = fmaxf(mA, fabsf(vA[i]));
            mB = fmaxf(mB, fabsf(vB[i]));
        }
        // block = 32 N-cols spread over the 4 lanes of this quad
        #pragma unroll
        for (int o = 1; o <= 2; o <<= 1) {
            mA = fmaxf(mA, __shfl_xor_sync(0xffffffffu, mA, o));
            mB = fmaxf(mB, __shfl_xor_sync(0xffffffffu, mB, o));
        }
        int seA = block_se(mA), seB = block_se(mB);
        long rowA = bRow + wRow + mi * 16 + g;
        long rowB = rowA + 8;
        long colBase = bCol + wCol + tg * 2;
        #pragma unroll
        for (int nj = 0; nj < 4; nj++) {
            __nv_bfloat162 pa, pb;
            pa.x = __float2bfloat16(block_quant(vA[nj*2+0], seA, 3, 7.5f));
            pa.y = __float2bfloat16(block_quant(vA[nj*2+1], seA, 3, 7.5f));
            pb.x = __float2bfloat16(block_quant(vB[nj*2+0], seB, 3, 7.5f));
            pb.y = __float2bfloat16(block_quant(vB[nj*2+1], seB, 3, 7.5f));
            *(__nv_bfloat162*)(O + rowA * (long)I_DIM + colBase + nj * 8) = pa;
            *(__nv_bfloat162*)(O + rowB * (long)I_DIM + colBase + nj * 8) = pb;
        }
    }
}

// ---------------------------------------------------------------------------
// Down GEMM: out[4096,2048] = Iq[4096,8192] @ Wdq[2048,8192]^T, fp32 out.
// Tile 128x128x32, 8 warps (4 over M x 2 over N), each warp 32x64.
// ---------------------------------------------------------------------------
__global__ __launch_bounds__(256) void gemm_down_kernel(float* __restrict__ C) {
    __shared__ __align__(128) __nv_bfloat16 sA[2][128][LDT];
    __shared__ __align__(128) __nv_bfloat16 sB[2][128][LDT];

    const __nv_bfloat16* A = g_Iq;
    const __nv_bfloat16* B = g_Wdq;
    const int K = I_DIM, N = H_DIM;

    int tid = threadIdx.x;
    long bRow = (long)blockIdx.y * 128;
    long bCol = (long)blockIdx.x * 128;
    int warp = tid >> 5, lane = tid & 31;
    int wRow = (warp & 3) * 32;
    int wCol = (warp >> 2) * 64;

    float acc[2][8][4];
    #pragma unroll
    for (int i = 0; i < 2; i++)
        #pragma unroll
        for (int j = 0; j < 8; j++)
            #pragma unroll
            for (int k = 0; k < 4; k++) acc[i][j][k] = 0.0f;

    const int nK = K / 32;  // 256

    auto load_stage = [&](int st, int k0) {
        #pragma unroll
        for (int i = 0; i < 2; i++) {
            int idx = i * 256 + tid;
            int r = idx >> 2, c = (idx & 3) * 8;
            cp16(&sA[st][r][c], A + (bRow + r) * (long)K + k0 + c);
            cp16(&sB[st][r][c], B + (bCol + r) * (long)K + k0 + c);
        }
    };

    load_stage(0, 0);
    cp_commit();

    for (int kt = 0; kt < nK; ++kt) {
        if (kt + 1 < nK) load_stage((kt + 1) & 1, (kt + 1) * 32);
        cp_commit();
        cp_wait1();
        __syncthreads();

        int st = kt & 1;
        #pragma unroll
        for (int ks = 0; ks < 32; ks += 16) {
            uint32_t af[2][4];
            #pragma unroll
            for (int mi = 0; mi < 2; mi++) {
                int row = wRow + mi * 16 + (lane & 15);
                int col = ks + ((lane >> 4) << 3);
                ldsm4(af[mi][0], af[mi][1], af[mi][2], af[mi][3], &sA[st][row][col]);
            }
            uint32_t bf[8][2];
            #pragma unroll
            for (int p = 0; p < 4; p++) {
                int row = wCol + p * 16 + ((lane >> 4) << 3) + (lane & 7);
                int col = ks + ((lane >> 3) & 1) * 8;
                ldsm4(bf[2*p][0], bf[2*p][1], bf[2*p+1][0], bf[2*p+1][1], &sB[st][row][col]);
            }
            #pragma unroll
            for (int mi = 0; mi < 2; mi++)
                #pragma unroll
                for (int nj = 0; nj < 8; nj++)
                    mma16816(acc[mi][nj], af[mi], bf[nj]);
        }
        __syncthreads();
    }

    int g = lane >> 2, tg = lane & 3;
    #pragma unroll
    for (int mi = 0; mi < 2; mi++)
        #pragma unroll
        for (int nj = 0; nj < 8; nj++) {
            long row = bRow + wRow + mi * 16 + g;
            long col = bCol + wCol + nj * 8 + tg * 2;
            *(float2*)(C + row * (long)N + col) =
                make_float2(acc[mi][nj][0], acc[mi][nj][1]);
            *(float2*)(C + (row + 8) * (long)N + col) =
                make_float2(acc[mi][nj][2], acc[mi][nj][3]);
        }
}

// ---------------------------------------------------------------------------
// Launch: pure kernel launches (graph-capturable, no runtime API calls).
// ---------------------------------------------------------------------------
extern "C" void kernel_launch(void* const* d_in, const int* in_sizes, int n_in,
                              void* d_out, int out_size) {
    (void)in_sizes; (void)n_in; (void)out_size;
    const float* x  = (const float*)d_in[0];
    const float* wg = (const float*)d_in[1];
    const float* wu = (const float*)d_in[2];
    const float* wd = (const float*)d_in[3];
    float* out = (float*)d_out;

    // 1) Quantize activations (fp6 grid) and weights (fp4 grid) to bf16.
    long nbA = (long)S_DIM * H_DIM / 32;   // 262144
    long nbW = (long)I_DIM * H_DIM / 32;   // 524288
    quant_mx_kernel<<<(int)(nbA / 8), 256>>>(x,  0, nbA, 3, 7.5f);
    quant_mx_kernel<<<(int)(nbW / 8), 256>>>(wg, 1, nbW, 1, 6.0f);
    quant_mx_kernel<<<(int)(nbW / 8), 256>>>(wu, 2, nbW, 1, 6.0f);
    quant_mx_kernel<<<(int)(nbW / 8), 256>>>(wd, 3, nbW, 1, 6.0f);

    // 2) Fused gate/up GEMM + SwiGLU + fp6 quant -> Iq.
    dim3 g1(I_DIM / 64, S_DIM / 128);      // (128, 32)
    gemm_gateup_swiglu_kernel<<<g1, 256>>>(x);

    // 3) out = Iq @ Wdq^T.
    dim3 g2(H_DIM / 128, S_DIM / 128);     // (16, 32)
    gemm_down_kernel<<<g2, 256>>>(out);
}

// round 6
// speedup vs baseline: 1.4819x; 1.4819x over previous
#include <cuda_runtime.h>
#include <cuda_bf16.h>
#include <cstdint>

// ---------------------------------------------------------------------------
// LlamaMLP with MX quantization (fp6_e2m3 activations, fp4_e2m1 weights).
// x[4096,2048], w_gate[8192,2048], w_up[8192,2048], w_down[2048,8192] -> out fp32.
//
// MX-quantized values (<=4 significand bits * power-of-2 block scale) are
// EXACTLY representable in bf16 => quantize once to bf16, then bf16 mma.sync
// GEMMs with fp32 accumulation (products exact; only sum order differs).
// NOTE: harness compiles for plain sm_100 (no 'a' suffix) => tcgen05 is
// unavailable; mma.sync.m16n8k16 is the tensor path.
//
//   1) one kernel quantizes x (fp6 grid) + all 3 weights (fp4 grid) [bit ops]
//   2) fused gate/up GEMM + SwiGLU + fp6 MX quant -> Iq (bf16)
//   3) down GEMM -> out fp32
// ---------------------------------------------------------------------------

#define S_DIM 4096
#define H_DIM 2048
#define I_DIM 8192

__device__ __align__(256) __nv_bfloat16 g_Aq [(size_t)S_DIM * H_DIM];  // 16 MB
__device__ __align__(256) __nv_bfloat16 g_Wgq[(size_t)I_DIM * H_DIM];  // 32 MB
__device__ __align__(256) __nv_bfloat16 g_Wuq[(size_t)I_DIM * H_DIM];  // 32 MB
__device__ __align__(256) __nv_bfloat16 g_Wdq[(size_t)H_DIM * I_DIM];  // 32 MB
__device__ __align__(256) __nv_bfloat16 g_Iq [(size_t)S_DIM * I_DIM];  // 64 MB

// ---------------------------------------------------------------------------
// Fast exact MX quant primitives (bit ops only; no MUFU, no div).
//   floor(log2|x|) == exponent_field - 127 for normals; for x==0/denormal the
//   clamps land on the same result as the reference (checked both branches).
// ---------------------------------------------------------------------------
__device__ __forceinline__ float p2f(int e) {           // 2^e, e in [-127,127]
    return __int_as_float((e + 127) << 23);
}
__device__ __forceinline__ int fexp(float x) {          // unbiased exponent field
    return (int)((__float_as_uint(x) >> 23) & 0xFF) - 127;
}
__device__ __forceinline__ float quant_elem_fast(float x, int mfrac, float maxn) {
    int e = max(fexp(fabsf(x)), 0);                     // e2 formats: min_exp = 0
    float r = rintf(x * p2f(mfrac - e)) * p2f(e - mfrac);
    return fminf(fmaxf(r, -maxn), maxn);
}
__device__ __forceinline__ int block_se_fast(float amax) {
    int se = fexp(amax) - 2;                            // emax_elem = 2
    return min(max(se, -127), 127);
}
__device__ __forceinline__ uint32_t pack_bf16x2(float a, float b) {
    return (uint32_t)__bfloat16_as_ushort(__float2bfloat16(a))
         | ((uint32_t)__bfloat16_as_ushort(__float2bfloat16(b)) << 16);
}

// One launch quantizes all four tensors. float4 per thread; MX block = 8 lanes.
#define N4X ((long)S_DIM * H_DIM / 4)   // 2097152
#define N4W ((long)I_DIM * H_DIM / 4)   // 4194304
#define N4TOT (N4X + 3 * N4W)           // 14680064

__global__ void quant_all_kernel(const float4* __restrict__ x,
                                 const float4* __restrict__ wg,
                                 const float4* __restrict__ wu,
                                 const float4* __restrict__ wd) {
    long i = (long)blockIdx.x * blockDim.x + threadIdx.x;
    if (i >= N4TOT) return;

    const float4* src; uint2* dst; long idx; int mfrac; float maxn;
    if (i < N4X) {
        src = x; dst = (uint2*)g_Aq; idx = i; mfrac = 3; maxn = 7.5f;
    } else {
        long j = i - N4X;
        int t = (int)(j / N4W);
        idx = j - (long)t * N4W;
        src = (t == 0) ? wg : (t == 1) ? wu : wd;
        dst = (uint2*)((t == 0) ? g_Wgq : (t == 1) ? g_Wuq : g_Wdq);
        mfrac = 1; maxn = 6.0f;
    }

    float4 v = src[idx];
    float a = fmaxf(fmaxf(fabsf(v.x), fabsf(v.y)), fmaxf(fabsf(v.z), fabsf(v.w)));
    a = fmaxf(a, __shfl_xor_sync(0xffffffffu, a, 1));
    a = fmaxf(a, __shfl_xor_sync(0xffffffffu, a, 2));
    a = fmaxf(a, __shfl_xor_sync(0xffffffffu, a, 4));
    int se = block_se_fast(a);
    float inv = p2f(-se), sc = p2f(se);
    uint2 o;
    o.x = pack_bf16x2(quant_elem_fast(v.x * inv, mfrac, maxn) * sc,
                      quant_elem_fast(v.y * inv, mfrac, maxn) * sc);
    o.y = pack_bf16x2(quant_elem_fast(v.z * inv, mfrac, maxn) * sc,
                      quant_elem_fast(v.w * inv, mfrac, maxn) * sc);
    dst[idx] = o;
}

// ---------------------------------------------------------------------------
// GEMM building blocks: mma.m16n8k16 bf16, cp.async, ldmatrix.
// SMEM rows padded to 40 halves (80 B) -> conflict-free ldmatrix.
// ---------------------------------------------------------------------------
#define LDT 40

__device__ __forceinline__ void cp16(uint32_t d, const void* s) {
    asm volatile("cp.async.cg.shared.global [%0], [%1], 16;" :: "r"(d), "l"(s));
}
__device__ __forceinline__ void cp_commit() { asm volatile("cp.async.commit_group;"); }
template <int N>
__device__ __forceinline__ void cp_wait() { asm volatile("cp.async.wait_group %0;" :: "n"(N)); }

__device__ __forceinline__ void ldsm4(uint32_t& r0, uint32_t& r1, uint32_t& r2,
                                      uint32_t& r3, uint32_t a) {
    asm volatile("ldmatrix.sync.aligned.m8n8.x4.shared.b16 {%0,%1,%2,%3}, [%4];"
                 : "=r"(r0), "=r"(r1), "=r"(r2), "=r"(r3) : "r"(a));
}
__device__ __forceinline__ void mma16816(float* c, const uint32_t* a, const uint32_t* b) {
    asm volatile(
        "mma.sync.aligned.m16n8k16.row.col.f32.bf16.bf16.f32 "
        "{%0,%1,%2,%3}, {%4,%5,%6,%7}, {%8,%9}, {%0,%1,%2,%3};"
        : "+f"(c[0]), "+f"(c[1]), "+f"(c[2]), "+f"(c[3])
        : "r"(a[0]), "r"(a[1]), "r"(a[2]), "r"(a[3]), "r"(b[0]), "r"(b[1]));
}
__device__ __forceinline__ uint32_t smem_u32(const void* p) {
    return (uint32_t)__cvta_generic_to_shared(p);
}

#define NSTG 4

// ---------------------------------------------------------------------------
// Fused gate/up GEMM + SwiGLU + fp6 MX quant.
// CTA: M=128 x N=64 (per matrix), K-tile 32, 8 warps (4 over M, 2 over N).
// Warp's 32 N-cols == one MX block per row. 4-stage cp.async, 2 CTAs/SM.
// Stage layout (bf16): A[128][40] @0, Bg[64][40] @10240B, Bu[64][40] @15360B.
// ---------------------------------------------------------------------------
#define GU_STG 20480

__global__ __launch_bounds__(256, 2) void gateup_mma_kernel() {
    extern __shared__ __align__(16) char smem_raw[];
    uint32_t s0 = smem_u32(smem_raw);

    const __nv_bfloat16* A  = g_Aq;
    const __nv_bfloat16* Bg = g_Wgq;
    const __nv_bfloat16* Bu = g_Wuq;
    const int K = H_DIM;

    int tid = threadIdx.x;
    long bRow = (long)blockIdx.y * 128;
    long bCol = (long)blockIdx.x * 64;
    int warp = tid >> 5, lane = tid & 31;
    int wRow = (warp & 3) * 32;
    int wCol = (warp >> 2) * 32;

    float ag[2][4][4], au[2][4][4];
    #pragma unroll
    for (int i = 0; i < 2; i++)
        #pragma unroll
        for (int j = 0; j < 4; j++)
            #pragma unroll
            for (int k = 0; k < 4; k++) { ag[i][j][k] = 0.0f; au[i][j][k] = 0.0f; }

    const int nK = K / 32;  // 64

    auto load_stage = [&](int j) {
        uint32_t base = s0 + (uint32_t)(j & (NSTG - 1)) * GU_STG;
        int k0 = j * 32;
        #pragma unroll
        for (int i = 0; i < 2; i++) {                 // A: 128 rows x 32 cols
            int id = i * 256 + tid, r = id >> 2, cc = id & 3;
            cp16(base + r * 80 + cc * 16, A + (bRow + r) * (long)K + k0 + cc * 8);
        }
        {                                             // Bg: 64 rows
            int r = tid >> 2, cc = tid & 3;
            cp16(base + 10240 + r * 80 + cc * 16, Bg + (bCol + r) * (long)K + k0 + cc * 8);
            cp16(base + 15360 + r * 80 + cc * 16, Bu + (bCol + r) * (long)K + k0 + cc * 8);
        }
    };

    load_stage(0); cp_commit();
    load_stage(1); cp_commit();
    load_stage(2); cp_commit();

    for (int kt = 0; kt < nK; ++kt) {
        cp_wait<2>();          // stage kt resident
        __syncthreads();       // all warps done with stage kt-1's buffer + see data
        if (kt + 3 < nK) load_stage(kt + 3);
        cp_commit();           // uniform group count (empty near tail)

        uint32_t base = s0 + (uint32_t)(kt & (NSTG - 1)) * GU_STG;
        #pragma unroll
        for (int ks = 0; ks < 32; ks += 16) {
            uint32_t af[2][4];
            #pragma unroll
            for (int mi = 0; mi < 2; mi++) {
                int row = wRow + mi * 16 + (lane & 15);
                int col = ks + ((lane >> 4) << 3);
                ldsm4(af[mi][0], af[mi][1], af[mi][2], af[mi][3],
                      base + row * 80 + col * 2);
            }
            uint32_t bg[4][2], bu[4][2];
            #pragma unroll
            for (int p = 0; p < 2; p++) {
                int row = wCol + p * 16 + ((lane >> 4) << 3) + (lane & 7);
                int col = ks + ((lane >> 3) & 1) * 8;
                ldsm4(bg[2*p][0], bg[2*p][1], bg[2*p+1][0], bg[2*p+1][1],
                      base + 10240 + row * 80 + col * 2);
                ldsm4(bu[2*p][0], bu[2*p][1], bu[2*p+1][0], bu[2*p+1][1],
                      base + 15360 + row * 80 + col * 2);
            }
            #pragma unroll
            for (int mi = 0; mi < 2; mi++)
                #pragma unroll
                for (int nj = 0; nj < 4; nj++) {
                    mma16816(ag[mi][nj], af[mi], bg[nj]);
                    mma16816(au[mi][nj], af[mi], bu[nj]);
                }
        }
    }

    // ---- Epilogue: silu(gate)*up, MX fp6 quant per 32-wide N block ----
    __nv_bfloat16* O = g_Iq;
    int g = lane >> 2, tg = lane & 3;
    #pragma unroll
    for (int mi = 0; mi < 2; mi++) {
        float vA[8], vB[8];
        #pragma unroll
        for (int nj = 0; nj < 4; nj++)
            #pragma unroll
            for (int k = 0; k < 2; k++) {
                float gv = ag[mi][nj][k],    uv = au[mi][nj][k];
                vA[nj*2+k] = gv / (1.0f + expf(-gv)) * uv;
                float gv2 = ag[mi][nj][2+k], uv2 = au[mi][nj][2+k];
                vB[nj*2+k] = gv2 / (1.0f + expf(-gv2)) * uv2;
            }
        float mA = 0.0f, mB = 0.0f;
        #pragma unroll
        for (int i = 0; i < 8; i++) {
            mA = fmaxf(mA, fabsf(vA[i]));
            mB = fmaxf(mB, fabsf(vB[i]));
        }
        #pragma unroll
        for (int o = 1; o <= 2; o <<= 1) {   // block = 32 cols over the quad
            mA = fmaxf(mA, __shfl_xor_sync(0xffffffffu, mA, o));
            mB = fmaxf(mB, __shfl_xor_sync(0xffffffffu, mB, o));
        }
        int seA = block_se_fast(mA), seB = block_se_fast(mB);
        float invA = p2f(-seA), scA = p2f(seA);
        float invB = p2f(-seB), scB = p2f(seB);
        long rowA = bRow + wRow + mi * 16 + g;
        long rowB = rowA + 8;
        long colBase = bCol + wCol + tg * 2;
        #pragma unroll
        for (int nj = 0; nj < 4; nj++) {
            uint32_t pa = pack_bf16x2(
                quant_elem_fast(vA[nj*2+0] * invA, 3, 7.5f) * scA,
                quant_elem_fast(vA[nj*2+1] * invA, 3, 7.5f) * scA);
            uint32_t pb = pack_bf16x2(
                quant_elem_fast(vB[nj*2+0] * invB, 3, 7.5f) * scB,
                quant_elem_fast(vB[nj*2+1] * invB, 3, 7.5f) * scB);
            *(uint32_t*)(O + rowA * (long)I_DIM + colBase + nj * 8) = pa;
            *(uint32_t*)(O + rowB * (long)I_DIM + colBase + nj * 8) = pb;
        }
    }
}

// ---------------------------------------------------------------------------
// Down GEMM: out[4096,2048] = Iq[4096,8192] @ Wdq[2048,8192]^T, fp32.
// CTA 128x128, K-tile 32, 8 warps (4 over M x 2 over N), warp 32x64.
// Stage layout (bf16): A[128][40] @0, B[128][40] @10240B. 4 stages, 2 CTA/SM.
// ---------------------------------------------------------------------------
#define DN_STG 20480

__global__ __launch_bounds__(256, 2) void down_mma_kernel(float* __restrict__ C) {
    extern __shared__ __align__(16) char smem_raw[];
    uint32_t s0 = smem_u32(smem_raw);

    const __nv_bfloat16* A = g_Iq;
    const __nv_bfloat16* B = g_Wdq;
    const int K = I_DIM, N = H_DIM;

    int tid = threadIdx.x;
    long bRow = (long)blockIdx.y * 128;
    long bCol = (long)blockIdx.x * 128;
    int warp = tid >> 5, lane = tid & 31;
    int wRow = (warp & 3) * 32;
    int wCol = (warp >> 2) * 64;

    float acc[2][8][4];
    #pragma unroll
    for (int i = 0; i < 2; i++)
        #pragma unroll
        for (int j = 0; j < 8; j++)
            #pragma unroll
            for (int k = 0; k < 4; k++) acc[i][j][k] = 0.0f;

    const int nK = K / 32;  // 256

    auto load_stage = [&](int j) {
        uint32_t base = s0 + (uint32_t)(j & (NSTG - 1)) * DN_STG;
        int k0 = j * 32;
        #pragma unroll
        for (int i = 0; i < 2; i++) {
            int id = i * 256 + tid, r = id >> 2, cc = id & 3;
            cp16(base + r * 80 + cc * 16,         A + (bRow + r) * (long)K + k0 + cc * 8);
            cp16(base + 10240 + r * 80 + cc * 16, B + (bCol + r) * (long)K + k0 + cc * 8);
        }
    };

    load_stage(0); cp_commit();
    load_stage(1); cp_commit();
    load_stage(2); cp_commit();

    for (int kt = 0; kt < nK; ++kt) {
        cp_wait<2>();
        __syncthreads();
        if (kt + 3 < nK) load_stage(kt + 3);
        cp_commit();

        uint32_t base = s0 + (uint32_t)(kt & (NSTG - 1)) * DN_STG;
        #pragma unroll
        for (int ks = 0; ks < 32; ks += 16) {
            uint32_t af[2][4];
            #pragma unroll
            for (int mi = 0; mi < 2; mi++) {
                int row = wRow + mi * 16 + (lane & 15);
                int col = ks + ((lane >> 4) << 3);
                ldsm4(af[mi][0], af[mi][1], af[mi][2], af[mi][3],
                      base + row * 80 + col * 2);
            }
            uint32_t bf[8][2];
            #pragma unroll
            for (int p = 0; p < 4; p++) {
                int row = wCol + p * 16 + ((lane >> 4) << 3) + (lane & 7);
                int col = ks + ((lane >> 3) & 1) * 8;
                ldsm4(bf[2*p][0], bf[2*p][1], bf[2*p+1][0], bf[2*p+1][1],
                      base + 10240 + row * 80 + col * 2);
            }
            #pragma unroll
            for (int mi = 0; mi < 2; mi++)
                #pragma unroll
                for (int nj = 0; nj < 8; nj++)
                    mma16816(acc[mi][nj], af[mi], bf[nj]);
        }
    }

    int g = lane >> 2, tg = lane & 3;
    #pragma unroll
    for (int mi = 0; mi < 2; mi++)
        #pragma unroll
        for (int nj = 0; nj < 8; nj++) {
            long row = bRow + wRow + mi * 16 + g;
            long col = bCol + wCol + nj * 8 + tg * 2;
            *(float2*)(C + row * (long)N + col) =
                make_float2(acc[mi][nj][0], acc[mi][nj][1]);
            *(float2*)(C + (row + 8) * (long)N + col) =
                make_float2(acc[mi][nj][2], acc[mi][nj][3]);
        }
}

// ---------------------------------------------------------------------------
// Launch (3 kernel launches; attribute set is not a stream op, capture-safe).
// ---------------------------------------------------------------------------
#define GU_DYN (NSTG * GU_STG)   // 81920 B
#define DN_DYN (NSTG * DN_STG)   // 81920 B

extern "C" void kernel_launch(void* const* d_in, const int* in_sizes, int n_in,
                              void* d_out, int out_size) {
    (void)in_sizes; (void)n_in; (void)out_size;
    const float4* x  = (const float4*)d_in[0];
    const float4* wg = (const float4*)d_in[1];
    const float4* wu = (const float4*)d_in[2];
    const float4* wd = (const float4*)d_in[3];
    float* out = (float*)d_out;

    cudaFuncSetAttribute(gateup_mma_kernel,
                         cudaFuncAttributeMaxDynamicSharedMemorySize, GU_DYN);
    cudaFuncSetAttribute(down_mma_kernel,
                         cudaFuncAttributeMaxDynamicSharedMemorySize, DN_DYN);

    // 1) Quantize all four tensors in one launch.
    int qgrid = (int)((N4TOT + 255) / 256);   // 57344
    quant_all_kernel<<<qgrid, 256>>>(x, wg, wu, wd);

    // 2) Fused gate/up GEMM + SwiGLU + fp6 quant -> Iq.
    dim3 g1(I_DIM / 64, S_DIM / 128);         // (128, 32)
    gateup_mma_kernel<<<g1, 256, GU_DYN>>>();

    // 3) out = Iq @ Wdq^T.
    dim3 g2(H_DIM / 128, S_DIM / 128);        // (16, 32)
    down_mma_kernel<<<g2, 256, DN_DYN>>>(out);
}